// round 9
// baseline (speedup 1.0000x reference)
#include <cuda_runtime.h>

// CollisionLoss, f32x2-packed, 8 warp-roles per block (pairs split across
// warps in-block; staging done ONCE per 64-batch group).
// pos [B=65536, N=24, 3] f32 -> scalar f32.
// Per batch, masked pairs (i<j, i>=1, skip (2,3)):
//   sq = |p_i-p_j|^2 ; if sq < 0.25: sum += exp(-4*sq); cnt++
// out = (cnt>0 ? sum/cnt : 0) + 1e-6
// Coords pre-scaled at staging by s = sqrt(4*log2(e)); term = 2^(-sq'),
// test sq' < log2(e). Each thread = 2 batches (lo/hi f32x2 halves).
// FSEL tail (pred-as-data, lat 4) — predicated adds regressed (R7).
// vs R6 (19.2us): same staging + same total instrs, but 8 half-length warp
// roles instead of 4 -> resident warps 28->32/SM and per-warp serial chain
// halved. R7/R6 showed dur ~ serial_len/resident_warps.

typedef unsigned long long u64;

#define THREADS 256
#define FLOATS_PER 72
#define ROW_F2 73                 // float2 cells per lane row; 73 u64 stride ≡ 9 mod 16 -> LDS.64 conflict-free
#define BATCHES_PER_BLOCK 64
#define MAX_BLOCKS 1024

__device__ float g_psum[MAX_BLOCKS];
__device__ float g_pcnt[MAX_BLOCKS];
__device__ unsigned int g_ticket = 0;

__device__ __forceinline__ u64 f2_mul(u64 a, u64 b) {
    u64 d; asm("mul.rn.f32x2 %0, %1, %2;" : "=l"(d) : "l"(a), "l"(b)); return d;
}
__device__ __forceinline__ u64 f2_fma(u64 a, u64 b, u64 c) {
    u64 d; asm("fma.rn.f32x2 %0, %1, %2, %3;" : "=l"(d) : "l"(a), "l"(b), "l"(c)); return d;
}
__device__ __forceinline__ float nex2(float s) {   // 2^(-s)
    float e;
    asm("{\n\t.reg .f32 t;\n\tneg.f32 t, %1;\n\tex2.approx.f32 %0, t;\n\t}"
        : "=f"(e) : "f"(s));
    return e;
}

#define NEG1_F32X2 0xBF800000BF800000ULL

#define PAIR2(ix_, iy_, iz_, jx_, jy_, jz_)                           \
    do {                                                              \
        u64 d0 = f2_fma((jx_), NEG1, (ix_));   /* i - j */            \
        u64 d1 = f2_fma((jy_), NEG1, (iy_));                          \
        u64 d2 = f2_fma((jz_), NEG1, (iz_));                          \
        u64 s2 = f2_mul(d0, d0);                                      \
        s2 = f2_fma(d1, d1, s2);                                      \
        s2 = f2_fma(d2, d2, s2);           /* scaled sq >= 0 */       \
        float sl, sh;                                                 \
        asm("mov.b64 {%0, %1}, %2;" : "=f"(sl), "=f"(sh) : "l"(s2));  \
        float el = nex2(sl);                                          \
        float eh = nex2(sh);                                          \
        float wl = (sl < 1.44269504f) ? 1.0f : 0.0f;                  \
        float wh = (sh < 1.44269504f) ? 1.0f : 0.0f;                  \
        sum_lo = fmaf(el, wl, sum_lo);  cnt_lo += wl;                 \
        sum_hi = fmaf(eh, wh, sum_hi);  cnt_hi += wh;                 \
    } while (0)

// i in [I0, I1] preloaded packed; j streamed over [JLO, JHI]; only i<j pairs,
// (2,3) excluded at compile time.
template <int I0, int I1, int JLO, int JHI>
__device__ __forceinline__ void tri_stream(const u64* __restrict__ row, u64 NEG1,
                                           float& sum_lo, float& sum_hi,
                                           float& cnt_lo, float& cnt_hi) {
    const int NI = I1 - I0 + 1;
    u64 ix[NI], iy[NI], iz[NI];
    #pragma unroll
    for (int k = 0; k < NI; k++) {
        ix[k] = row[(I0 + k) * 3 + 0];
        iy[k] = row[(I0 + k) * 3 + 1];
        iz[k] = row[(I0 + k) * 3 + 2];
    }
    #pragma unroll
    for (int j = JLO; j <= JHI; j++) {
        u64 jx = row[j * 3 + 0];
        u64 jy = row[j * 3 + 1];
        u64 jz = row[j * 3 + 2];
        #pragma unroll
        for (int k = 0; k < NI; k++) {
            const int i = I0 + k;
            if (i >= j) continue;
            if (i == 2 && j == 3) continue;
            PAIR2(ix[k], iy[k], iz[k], jx, jy, jz);
        }
    }
}

__global__ __launch_bounds__(THREADS, 4)
void collision_w8_kernel(const float* __restrict__ pos, float* __restrict__ out, int B) {
    __shared__ float smf[32 * ROW_F2 * 2];      // 32 lanes x 73 float2 cells
    __shared__ float wsum[THREADS / 32];
    __shared__ float wcnt[THREADS / 32];
    __shared__ bool  amLast;

    const int tid   = threadIdx.x;
    const int role  = tid >> 5;                 // 0..7, warp-uniform
    const int lane  = tid & 31;
    const int bbase = blockIdx.x * BATCHES_PER_BLOCK;
    const int nvalid = min(BATCHES_PER_BLOCK, B - bbase);

    // ---- Stage once: coalesced float4 gmem -> interleaved (lo,hi) float2 smem ----
    {
        const float SCALE = 2.4022448929611436f;   // sqrt(4 * log2(e))
        const float4* src4 = reinterpret_cast<const float4*>(pos + (size_t)bbase * FLOATS_PER);
        const int n4 = nvalid * 18;
        for (int q = tid; q < BATCHES_PER_BLOCK * 18; q += THREADS) {
            float4 v = make_float4(0.f, 0.f, 0.f, 0.f);
            if (q < n4) v = src4[q];
            int bl = q / 18;
            int w4 = q - bl * 18;
            int ln = bl & 31, hf = bl >> 5;
            float* d = &smf[((ln * ROW_F2 + (w4 << 2)) << 1) + hf];
            d[0] = v.x * SCALE; d[2] = v.y * SCALE;
            d[4] = v.z * SCALE; d[6] = v.w * SCALE;
        }
    }
    __syncthreads();

    const u64 NEG1 = NEG1_F32X2;
    float sum_lo = 0.0f, sum_hi = 0.0f, cnt_lo = 0.0f, cnt_hi = 0.0f;

    {
        const u64* row = reinterpret_cast<const u64*>(&smf[lane * ROW_F2 * 2]);
        // 8 roles = R6's 4 roles each split in two. Pairs/role:
        // 29 / 33 / 34 / 36 / 34 / 30 / 26 / 30  (total 252)
        switch (role) {
            case 0: tri_stream<1, 3, 2, 12>(row, NEG1, sum_lo, sum_hi, cnt_lo, cnt_hi);  break;
            case 1: tri_stream<1, 3, 13, 23>(row, NEG1, sum_lo, sum_hi, cnt_lo, cnt_hi); break;
            case 2: tri_stream<4, 7, 5, 14>(row, NEG1, sum_lo, sum_hi, cnt_lo, cnt_hi);  break;
            case 3: tri_stream<4, 7, 15, 23>(row, NEG1, sum_lo, sum_hi, cnt_lo, cnt_hi); break;
            case 4: tri_stream<8, 11, 9, 18>(row, NEG1, sum_lo, sum_hi, cnt_lo, cnt_hi); break;
            case 5:
                tri_stream<8, 11, 19, 23>(row, NEG1, sum_lo, sum_hi, cnt_lo, cnt_hi);    // 20
                tri_stream<19, 22, 20, 23>(row, NEG1, sum_lo, sum_hi, cnt_lo, cnt_hi);   // 10
                break;
            case 6: tri_stream<12, 15, 13, 20>(row, NEG1, sum_lo, sum_hi, cnt_lo, cnt_hi); break;
            default:
                tri_stream<12, 15, 21, 23>(row, NEG1, sum_lo, sum_hi, cnt_lo, cnt_hi);   // 12
                tri_stream<16, 18, 17, 23>(row, NEG1, sum_lo, sum_hi, cnt_lo, cnt_hi);   // 18
                break;
        }
    }

    // Validity gating (zero-padded halves can't contribute).
    const bool vlo = (bbase + lane) < B;
    const bool vhi = (bbase + 32 + lane) < B;
    float lsum = (vlo ? sum_lo : 0.0f) + (vhi ? sum_hi : 0.0f);
    float lcnt = (vlo ? cnt_lo : 0.0f) + (vhi ? cnt_hi : 0.0f);

    // ---- Block reduce ----
    #pragma unroll
    for (int o = 16; o > 0; o >>= 1) {
        lsum += __shfl_down_sync(0xffffffffu, lsum, o);
        lcnt += __shfl_down_sync(0xffffffffu, lcnt, o);
    }
    if (lane == 0) { wsum[role] = lsum; wcnt[role] = lcnt; }
    __syncthreads();
    if (tid == 0) {
        float s = 0.0f, c = 0.0f;
        #pragma unroll
        for (int w = 0; w < THREADS / 32; w++) { s += wsum[w]; c += wcnt[w]; }
        g_psum[blockIdx.x] = s;
        g_pcnt[blockIdx.x] = c;
        __threadfence();
        unsigned int t = atomicAdd(&g_ticket, 1u);
        amLast = (t == gridDim.x - 1);
    }
    __syncthreads();

    // ---- Last block finalizes ----
    if (amLast) {
        const int nb = gridDim.x;
        float s = 0.0f, c = 0.0f;
        for (int i = tid; i < nb; i += THREADS) {
            s += g_psum[i];
            c += g_pcnt[i];
        }
        #pragma unroll
        for (int o = 16; o > 0; o >>= 1) {
            s += __shfl_down_sync(0xffffffffu, s, o);
            c += __shfl_down_sync(0xffffffffu, c, o);
        }
        if (lane == 0) { wsum[role] = s; wcnt[role] = c; }
        __syncthreads();
        if (tid == 0) {
            float ts = 0.0f, tc = 0.0f;
            #pragma unroll
            for (int w = 0; w < THREADS / 32; w++) { ts += wsum[w]; tc += wcnt[w]; }
            float total = (tc > 0.0f) ? (ts / fmaxf(tc, 1.0f)) : 0.0f;
            out[0] = total + 1e-6f;
            g_ticket = 0;   // reset for next graph replay
        }
    }
}

extern "C" void kernel_launch(void* const* d_in, const int* in_sizes, int n_in,
                              void* d_out, int out_size) {
    const float* pos = (const float*)d_in[0];
    const int B = in_sizes[0] / FLOATS_PER;
    int nblocks = (B + BATCHES_PER_BLOCK - 1) / BATCHES_PER_BLOCK;   // 1024 for B=65536
    if (nblocks > MAX_BLOCKS) nblocks = MAX_BLOCKS;
    collision_w8_kernel<<<nblocks, THREADS>>>(pos, (float*)d_out, B);
}

// round 10
// speedup vs baseline: 1.5384x; 1.5384x over previous
#include <cuda_runtime.h>

// CollisionLoss, f32x2-packed, MUFU-FREE (polynomial exp).
// pos [B=65536, N=24, 3] f32 -> scalar f32.
// Per batch, masked pairs (i<j, i>=1, skip (2,3)):
//   sq = |p_i-p_j|^2 ; if sq < 0.25: sum += exp(-4*sq); cnt++
// out = (cnt>0 ? sum/cnt : 0) + 1e-6
// Coords pre-scaled at staging by sqrt(4*log2 e): term = 2^(-s), test s < log2 e.
// KEY CHANGE vs R6 (19.2us best): 2^(-s) computed by a degree-5 Taylor poly
// about the interval midpoint, evaluated PACKED (f32x2) -> zero MUFU ops.
// Rationale: issue has been pinned at ~32% across occ 24..71% -> shared
// throughput throttle; EX2 goes through MUFU/MIO (rt 8/SMSP), 252/batch.
// Out-of-range s gives a finite poly value that is multiplied by w=0.
// Accumulators are packed too (FMA2/ADD2 tail).

typedef unsigned long long u64;

#define THREADS 128
#define FLOATS_PER 72
#define ROW_F2 73                 // float2 cells per lane row (72 + 1 pad)
#define BATCHES_PER_BLOCK 64
#define MAX_BLOCKS 1024

__device__ float g_psum[MAX_BLOCKS];
__device__ float g_pcnt[MAX_BLOCKS];
__device__ unsigned int g_ticket = 0;

__device__ __forceinline__ u64 f2_mul(u64 a, u64 b) {
    u64 d; asm("mul.rn.f32x2 %0, %1, %2;" : "=l"(d) : "l"(a), "l"(b)); return d;
}
__device__ __forceinline__ u64 f2_add(u64 a, u64 b) {
    u64 d; asm("add.rn.f32x2 %0, %1, %2;" : "=l"(d) : "l"(a), "l"(b)); return d;
}
__device__ __forceinline__ u64 f2_fma(u64 a, u64 b, u64 c) {
    u64 d; asm("fma.rn.f32x2 %0, %1, %2, %3;" : "=l"(d) : "l"(a), "l"(b), "l"(c)); return d;
}
__device__ __forceinline__ u64 pack2f(float f) {
    u64 r; asm("mov.b64 %0, {%1, %1};" : "=l"(r) : "f"(f)); return r;
}

#define NEG1_F32X2 0xBF800000BF800000ULL

// Poly context: 2^(-s) = K * e^(-c*u), u = s - M, c = ln2, M = 0.5/ln2.
// Degree-5 Taylor in u; |c*u| <= 0.5 on the valid domain s in [0, log2 e].
struct PolyC {
    u64 NEG1, NEGM, B5, B4, B3, B2, B1, B0;
};
__device__ __forceinline__ PolyC make_poly() {
    PolyC p;
    p.NEG1 = NEG1_F32X2;
    p.NEGM = pack2f(-0.72134752044448f);      // -M
    p.B5   = pack2f(-8.0871094e-4f);          // K*(-c)^5/120
    p.B4   = pack2f( 5.8337404e-3f);          // K*c^4/24
    p.B3   = pack2f(-3.3664859e-2f);          // K*(-c)^3/6
    p.B2   = pack2f( 1.4570678e-1f);          // K*c^2/2
    p.B1   = pack2f(-4.2040941e-1f);          // -K*c
    p.B0   = pack2f( 6.0653066e-1f);          // K = e^-0.5
    return p;
}

// One packed pair (2 real pairs). Packed accumulators sum2/cnt2.
#define PAIR2(ix_, iy_, iz_, jx_, jy_, jz_)                             \
    do {                                                                \
        u64 d0 = f2_fma((jx_), pc.NEG1, (ix_));   /* i - j */           \
        u64 d1 = f2_fma((jy_), pc.NEG1, (iy_));                         \
        u64 d2 = f2_fma((jz_), pc.NEG1, (iz_));                         \
        u64 s2 = f2_mul(d0, d0);                                        \
        s2 = f2_fma(d1, d1, s2);                                        \
        s2 = f2_fma(d2, d2, s2);              /* scaled sq >= 0 */      \
        u64 uu = f2_add(s2, pc.NEGM);         /* u = s - M */           \
        u64 pp = f2_fma(pc.B5, uu, pc.B4);    /* Horner deg-5 */        \
        pp = f2_fma(pp, uu, pc.B3);                                     \
        pp = f2_fma(pp, uu, pc.B2);                                     \
        pp = f2_fma(pp, uu, pc.B1);                                     \
        pp = f2_fma(pp, uu, pc.B0);           /* ~= 2^(-s) on domain */ \
        float sl, sh;                                                   \
        asm("mov.b64 {%0, %1}, %2;" : "=f"(sl), "=f"(sh) : "l"(s2));    \
        float wl = (sl < 1.44269504f) ? 1.0f : 0.0f;                    \
        float wh = (sh < 1.44269504f) ? 1.0f : 0.0f;                    \
        u64 w2;                                                         \
        asm("mov.b64 %0, {%1, %2};" : "=l"(w2) : "f"(wl), "f"(wh));     \
        sum2 = f2_fma(pp, w2, sum2);                                    \
        cnt2 = f2_add(cnt2, w2);                                        \
    } while (0)

// i in [I0, I1] preloaded packed; j streamed over (I0, 23]; i<j pairs,
// (2,3) excluded at compile time.
template <int I0, int I1>
__device__ __forceinline__ void tri_stream(const u64* __restrict__ row,
                                           const PolyC& pc,
                                           u64& sum2, u64& cnt2) {
    const int NI = I1 - I0 + 1;
    u64 ix[NI], iy[NI], iz[NI];
    #pragma unroll
    for (int k = 0; k < NI; k++) {
        ix[k] = row[(I0 + k) * 3 + 0];
        iy[k] = row[(I0 + k) * 3 + 1];
        iz[k] = row[(I0 + k) * 3 + 2];
    }
    #pragma unroll
    for (int j = I0 + 1; j <= 23; j++) {
        u64 jx = row[j * 3 + 0];
        u64 jy = row[j * 3 + 1];
        u64 jz = row[j * 3 + 2];
        #pragma unroll
        for (int k = 0; k < NI; k++) {
            const int i = I0 + k;
            if (i >= j) continue;             // compile-time
            if (i == 2 && j == 3) continue;   // excluded pair, compile-time
            PAIR2(ix[k], iy[k], iz[k], jx, jy, jz);
        }
    }
}

__global__ __launch_bounds__(THREADS, 8)
void collision_poly_kernel(const float* __restrict__ pos, float* __restrict__ out, int B) {
    __shared__ float smf[32 * ROW_F2 * 2];      // 32 lanes x 73 float2 cells
    __shared__ float wsum[THREADS / 32];
    __shared__ float wcnt[THREADS / 32];
    __shared__ bool  amLast;

    const int tid   = threadIdx.x;
    const int role  = tid >> 5;
    const int lane  = tid & 31;
    const int bbase = blockIdx.x * BATCHES_PER_BLOCK;
    const int nvalid = min(BATCHES_PER_BLOCK, B - bbase);

    // ---- Stage: coalesced float4 gmem -> interleaved (lo,hi) float2 smem ----
    {
        const float SCALE = 2.4022448929611436f;   // sqrt(4 * log2 e)
        const float4* src4 = reinterpret_cast<const float4*>(pos + (size_t)bbase * FLOATS_PER);
        const int n4 = nvalid * 18;
        for (int q = tid; q < BATCHES_PER_BLOCK * 18; q += THREADS) {
            float4 v = make_float4(0.f, 0.f, 0.f, 0.f);
            if (q < n4) v = src4[q];
            int bl = q / 18;
            int w4 = q - bl * 18;
            int ln = bl & 31, hf = bl >> 5;
            float* d = &smf[((ln * ROW_F2 + (w4 << 2)) << 1) + hf];
            d[0] = v.x * SCALE; d[2] = v.y * SCALE;
            d[4] = v.z * SCALE; d[6] = v.w * SCALE;
        }
    }
    __syncthreads();

    const PolyC pc = make_poly();
    u64 sum2 = 0, cnt2 = 0;                      // packed (lo,hi) accumulators

    {
        const u64* row = reinterpret_cast<const u64*>(&smf[lane * ROW_F2 * 2]);
        if (role == 0) {
            tri_stream<1, 3>(row, pc, sum2, cnt2);    // 62 packed pairs
        } else if (role == 1) {
            tri_stream<4, 7>(row, pc, sum2, cnt2);    // 70
        } else if (role == 2) {
            tri_stream<8, 11>(row, pc, sum2, cnt2);   // 54
            tri_stream<19, 22>(row, pc, sum2, cnt2);  // 10
        } else {
            tri_stream<12, 15>(row, pc, sum2, cnt2);  // 38
            tri_stream<16, 18>(row, pc, sum2, cnt2);  // 18
        }
    }

    // Unpack + validity gating (zero-padded halves can't contribute).
    float sum_lo, sum_hi, cnt_lo, cnt_hi;
    asm("mov.b64 {%0, %1}, %2;" : "=f"(sum_lo), "=f"(sum_hi) : "l"(sum2));
    asm("mov.b64 {%0, %1}, %2;" : "=f"(cnt_lo), "=f"(cnt_hi) : "l"(cnt2));
    const bool vlo = (bbase + lane) < B;
    const bool vhi = (bbase + 32 + lane) < B;
    float lsum = (vlo ? sum_lo : 0.0f) + (vhi ? sum_hi : 0.0f);
    float lcnt = (vlo ? cnt_lo : 0.0f) + (vhi ? cnt_hi : 0.0f);

    // ---- Block reduce ----
    #pragma unroll
    for (int o = 16; o > 0; o >>= 1) {
        lsum += __shfl_down_sync(0xffffffffu, lsum, o);
        lcnt += __shfl_down_sync(0xffffffffu, lcnt, o);
    }
    if (lane == 0) { wsum[role] = lsum; wcnt[role] = lcnt; }
    __syncthreads();
    if (tid == 0) {
        float s = 0.0f, c = 0.0f;
        #pragma unroll
        for (int w = 0; w < THREADS / 32; w++) { s += wsum[w]; c += wcnt[w]; }
        g_psum[blockIdx.x] = s;
        g_pcnt[blockIdx.x] = c;
        __threadfence();
        unsigned int t = atomicAdd(&g_ticket, 1u);
        amLast = (t == gridDim.x - 1);
    }
    __syncthreads();

    // ---- Last block finalizes ----
    if (amLast) {
        const int nb = gridDim.x;
        float s = 0.0f, c = 0.0f;
        for (int i = tid; i < nb; i += THREADS) {
            s += g_psum[i];
            c += g_pcnt[i];
        }
        #pragma unroll
        for (int o = 16; o > 0; o >>= 1) {
            s += __shfl_down_sync(0xffffffffu, s, o);
            c += __shfl_down_sync(0xffffffffu, c, o);
        }
        if (lane == 0) { wsum[role] = s; wcnt[role] = c; }
        __syncthreads();
        if (tid == 0) {
            float ts = 0.0f, tc = 0.0f;
            #pragma unroll
            for (int w = 0; w < THREADS / 32; w++) { ts += wsum[w]; tc += wcnt[w]; }
            float total = (tc > 0.0f) ? (ts / fmaxf(tc, 1.0f)) : 0.0f;
            out[0] = total + 1e-6f;
            g_ticket = 0;   // reset for next graph replay
        }
    }
}

extern "C" void kernel_launch(void* const* d_in, const int* in_sizes, int n_in,
                              void* d_out, int out_size) {
    const float* pos = (const float*)d_in[0];
    const int B = in_sizes[0] / FLOATS_PER;
    int nblocks = (B + BATCHES_PER_BLOCK - 1) / BATCHES_PER_BLOCK;   // 1024 for B=65536
    if (nblocks > MAX_BLOCKS) nblocks = MAX_BLOCKS;
    collision_poly_kernel<<<nblocks, THREADS>>>(pos, (float*)d_out, B);
}